// round 4
// baseline (speedup 1.0000x reference)
#include <cuda_runtime.h>

#define N_SYM 128
#define LEVERAGE 30.0f
#define PF 4   // prefetch depth (iterations of float4 load buffers in flight)

__device__ __forceinline__ float step1(float f, float e, float p, float m,
                                       float um, float st, float rst,
                                       float mn, float mx, float& um_out)
{
    float tm  = m * LEVERAGE;
    float us  = um * tm;
    float mps = fabsf(p) + us;
    float adj = fminf((p * f > 0.0f) ? us : mps, 0.0f);
    float nps = f * (mps - adj);
    float an  = fabsf(nps);
    an = floorf(an * rst) * st;
    an = (an < mn) ? 0.0f : an;
    an = fminf(an, mx);
    um_out = __fdividef(mps - an, tm);
    return (e > 0.5f) ? copysignf(an, nps) : p;
}

__global__ void __launch_bounds__(64)
lowlevel_scan_kernel(
    const float4* __restrict__ F,   // [N_SYM, B4]
    const float4* __restrict__ E,
    const float4* __restrict__ P,
    const float4* __restrict__ M,
    const float4* __restrict__ UM,  // [B4]
    const float*  __restrict__ msm_min,
    const float*  __restrict__ msm_step,
    const float*  __restrict__ msm_max,
    float4* __restrict__ out_nps,   // [N_SYM, B4]
    float4* __restrict__ out_um,    // [B4] or nullptr
    int B4)
{
    __shared__ float s_mn[N_SYM];
    __shared__ float s_st[N_SYM];
    __shared__ float s_rst[N_SYM];
    __shared__ float s_mx[N_SYM];

    for (int i = threadIdx.x; i < N_SYM; i += blockDim.x) {
        float st = msm_step[i];
        s_st[i]  = st;
        s_rst[i] = 1.0f / st;
        s_mn[i]  = msm_min[i];
        s_mx[i]  = msm_max[i];
    }
    __syncthreads();

    int c = blockIdx.x * blockDim.x + threadIdx.x;
    if (c >= B4) return;

    float4 um = UM[c];

    // Rotating register buffers: PF iterations of loads in flight.
    float4 bf[PF], be[PF], bp[PF], bm[PF];
#pragma unroll
    for (int i = 0; i < PF; ++i) {
        int id = i * B4 + c;
        bf[i] = F[id]; be[i] = E[id]; bp[i] = P[id]; bm[i] = M[id];
    }

#pragma unroll 4
    for (int s = 0; s < N_SYM; ++s) {
        int j = s & (PF - 1);
        float4 f = bf[j], e = be[j], p = bp[j], m = bm[j];

        if (s + PF < N_SYM) {
            int id = (s + PF) * B4 + c;
            bf[j] = F[id]; be[j] = E[id]; bp[j] = P[id]; bm[j] = M[id];
        }

        float st = s_st[s], rst = s_rst[s], mn = s_mn[s], mx = s_mx[s];

        float4 o;
        o.x = step1(f.x, e.x, p.x, m.x, um.x, st, rst, mn, mx, um.x);
        o.y = step1(f.y, e.y, p.y, m.y, um.y, st, rst, mn, mx, um.y);
        o.z = step1(f.z, e.z, p.z, m.z, um.z, st, rst, mn, mx, um.z);
        o.w = step1(f.w, e.w, p.w, m.w, um.w, st, rst, mn, mx, um.w);
        out_nps[s * B4 + c] = o;
    }

    if (out_um != nullptr) out_um[c] = um;
}

extern "C" void kernel_launch(void* const* d_in, const int* in_sizes, int n_in,
                              void* d_out, int out_size)
{
    const float* fractions     = (const float*)d_in[0];
    const float* exec_samples  = (const float*)d_in[1];
    const float* pos_sizes     = (const float*)d_in[2];
    const float* margin_rates  = (const float*)d_in[3];
    const float* unused_margin = (const float*)d_in[4];
    const float* msm_min       = (const float*)d_in[5];
    const float* msm_step      = (const float*)d_in[6];
    const float* msm_max       = (const float*)d_in[7];

    int B  = in_sizes[4];     // BATCH
    int B4 = B / 4;           // float4 columns

    float* out_nps = (float*)d_out;
    float* out_um  = nullptr;
    if ((long long)out_size >= (long long)N_SYM * B + B)
        out_um = out_nps + (size_t)N_SYM * B;

    int threads = 64;
    int blocks  = (B4 + threads - 1) / threads;
    lowlevel_scan_kernel<<<blocks, threads>>>(
        (const float4*)fractions, (const float4*)exec_samples,
        (const float4*)pos_sizes, (const float4*)margin_rates,
        (const float4*)unused_margin,
        msm_min, msm_step, msm_max,
        (float4*)out_nps, (float4*)out_um, B4);
}